// round 12
// baseline (speedup 1.0000x reference)
#include <cuda_runtime.h>
#include <math.h>

// Shapelet_66932770341112 on sm_103a
// B=16, C=8, T=512, L=24, STRIDE=2, N=64, M=245, EPS=1
// d(b,m,n,c) = (1/L) * sum_l |x[b,c,2m+l] - w[n,c,l]| * pcm[c,m]
// out[0 : B*N*C]       = exp(-(min_m |d|)^2)
// out[B*N*C : 2*B*N*C] = min_m d

#define BB 16
#define CC 8
#define TT 512
#define LL 24
#define NN 64
#define MM 245
#define NBLK 8             // n per block

typedef unsigned long long ull;

__device__ __forceinline__ ull add_f32x2(ull a, ull b) {
    ull r;
    asm("add.rn.f32x2 %0, %1, %2;" : "=l"(r) : "l"(a), "l"(b));
    return r;
}
__device__ __forceinline__ float lo32(ull v) { return __int_as_float((unsigned)(v & 0xffffffffULL)); }
__device__ __forceinline__ float hi32(ull v) { return __int_as_float((unsigned)(v >> 32)); }

struct WTile { ull p[6]; };   // one shapelet's 12 weight pairs (24 regs)

__device__ __forceinline__ void load_tile(WTile& t, const ull* wrow) {
    const ulonglong2* w2 = (const ulonglong2*)wrow;
#pragma unroll
    for (int k = 0; k < 3; ++k) {
        const ulonglong2 v = w2[k * 2];
        const ulonglong2 u = w2[k * 2 + 1];
        t.p[2 * k]     = v.x;  // careful: keep pair order p[0..5] == wpairs 0,2,4,6,8,10? no:
        t.p[2 * k + 1] = v.y;
        (void)u;
    }
}

// d-accumulation for one shapelet tile against the thread's window.
__device__ __forceinline__ float accum(const ull* xw, const WTile& t) {
    float a0 = 0.f, a1 = 0.f, a2 = 0.f, a3 = 0.f;
#pragma unroll
    for (int k = 0; k < 6; ++k) {
        const ull d = add_f32x2(xw[k * 2],     t.p[k]);   // placeholder; real body below
        a0 += fabsf(lo32(d));
        a1 += fabsf(hi32(d));
        (void)a2; (void)a3;
    }
    return (a0 + a1) + (a2 + a3);
}

__global__ __launch_bounds__(256, 3)
void shapelet_kernel(const float* __restrict__ x,
                     const float* __restrict__ w,
                     const float* __restrict__ pcm,
                     float* __restrict__ out)
{
    __shared__ ull   xsm[268];             // x pairs: pair(t)=(x[2t],x[2t+1]) + pad
    __shared__ ull   wneg[NBLK][12];       // 8 shapelets, negated, as pairs
    __shared__ float dsm[NBLK][256];       // d(m) per local n

    const int bc   = blockIdx.x;           // b*C + c
    const int b    = bc >> 3;
    const int c    = bc & 7;
    const int n0   = blockIdx.y * NBLK;
    const int tid  = threadIdx.x;           // == m
    const int lane = tid & 31;
    const int warp = tid >> 5;              // 0..7

    ((float2*)xsm)[tid] = ((const float2*)(x + bc * TT))[tid];
    if (tid < 12) ((float2*)xsm)[256 + tid] = make_float2(0.f, 0.f);

    if (tid < NBLK * LL) {
        const int j = tid / LL;
        const int l = tid % LL;
        ((float*)wneg)[j * LL + l] = -w[((n0 + j) * CC + c) * LL + l];
    }
    __syncthreads();

    // ---- register window: xw[k] = pair(m + k), k=0..11 ----
    const int m = tid;
    ull xw[12];
#pragma unroll
    for (int k = 0; k < 12; ++k) xw[k] = xsm[m + k];

    const float INF   = __int_as_float(0x7f800000);
    const float pen   = (m < MM) ? pcm[c * MM + m] * (1.0f / (float)LL) : 0.0f;
    const float guard = (m < MM) ? 0.0f : INF;

    // ---- ping-pong register double-buffer over weight tiles ----
    ull bufA[6], bufB[6];
#pragma unroll
    for (int k = 0; k < 6; ++k) {                 // preload tile 0 -> A
        bufA[k] = wneg[0][2 * k] ;                // p[k] holds wpair 2k (even pairs)
    }
    // We need all 12 pairs per tile; hold them as two halves (even k in pA, odd in pB
    // would split a tile). Simpler: full 12-pair buffers.
    ull A[12], Bf[12];
#pragma unroll
    for (int k = 0; k < 12; ++k) A[k] = wneg[0][k];

#pragma unroll
    for (int jp = 0; jp < NBLK; jp += 2) {
        // issue loads for tile jp+1 into B, then compute tile jp from A
#pragma unroll
        for (int k = 0; k < 12; ++k) Bf[k] = wneg[jp + 1][k];
        {
            float a0 = 0.f, a1 = 0.f, a2 = 0.f, a3 = 0.f;
#pragma unroll
            for (int k = 0; k < 6; ++k) {
                const ull t0 = add_f32x2(xw[2 * k],     A[2 * k]);
                const ull t1 = add_f32x2(xw[2 * k + 1], A[2 * k + 1]);
                a0 += fabsf(lo32(t0));  a1 += fabsf(hi32(t0));
                a2 += fabsf(lo32(t1));  a3 += fabsf(hi32(t1));
            }
            dsm[jp][m] = fmaf((a0 + a1) + (a2 + a3), pen, guard);
        }
        // issue loads for tile jp+2 into A (if any), then compute tile jp+1 from B
        if (jp + 2 < NBLK) {
#pragma unroll
            for (int k = 0; k < 12; ++k) A[k] = wneg[jp + 2][k];
        }
        {
            float a0 = 0.f, a1 = 0.f, a2 = 0.f, a3 = 0.f;
#pragma unroll
            for (int k = 0; k < 6; ++k) {
                const ull t0 = add_f32x2(xw[2 * k],     Bf[2 * k]);
                const ull t1 = add_f32x2(xw[2 * k + 1], Bf[2 * k + 1]);
                a0 += fabsf(lo32(t0));  a1 += fabsf(hi32(t0));
                a2 += fabsf(lo32(t1));  a3 += fabsf(hi32(t1));
            }
            dsm[jp + 1][m] = fmaf((a0 + a1) + (a2 + a3), pen, guard);
        }
    }
    __syncthreads();

    // ---- 8 warps: warp w reduces row w over 256 m values ----
    {
        const float* row = dsm[warp];
        float mn = INF, mna = INF;
#pragma unroll
        for (int i = 0; i < 8; ++i) {
            const float v = row[lane + i * 32];
            mn  = fminf(mn,  v);
            mna = fminf(mna, fabsf(v));
        }
#pragma unroll
        for (int off = 16; off; off >>= 1) {
            mn  = fminf(mn,  __shfl_xor_sync(0xffffffffu, mn,  off));
            mna = fminf(mna, __shfl_xor_sync(0xffffffffu, mna, off));
        }
        if (lane == 0) {
            const int n = n0 + warp;
            const int o = (b * NN + n) * CC + c;
            out[o] = expf(-(mna * mna));
            out[BB * NN * CC + o] = mn;
        }
    }
}

extern "C" void kernel_launch(void* const* d_in, const int* in_sizes, int n_in,
                              void* d_out, int out_size)
{
    const float* x   = (const float*)d_in[0];   // (B, C, T)
    const float* w   = (const float*)d_in[1];   // (N, C, L)
    const float* pcm = (const float*)d_in[2];   // (C, M)
    float* out = (float*)d_out;

    dim3 grid(BB * CC, NN / NBLK);              // 128 x 8 = 1024 blocks of 256 thr
    shapelet_kernel<<<grid, 256>>>(x, w, pcm, out);
}

// round 13
// speedup vs baseline: 1.0030x; 1.0030x over previous
#include <cuda_runtime.h>
#include <math.h>

// Shapelet_66932770341112 on sm_103a
// B=16, C=8, T=512, L=24, STRIDE=2, N=64, M=245, EPS=1
// d(b,m,n,c) = (1/L) * sum_l |x[b,c,2m+l] - w[n,c,l]| * pcm[c,m]
// out[0 : B*N*C]       = exp(-(min_m |d|)^2)
// out[B*N*C : 2*B*N*C] = min_m d

#define BB 16
#define CC 8
#define TT 512
#define LL 24
#define NN 64
#define MM 245
#define NBLK 16            // n per block

typedef unsigned long long ull;

__device__ __forceinline__ ull add_f32x2(ull a, ull b) {
    ull r;
    asm("add.rn.f32x2 %0, %1, %2;" : "=l"(r) : "l"(a), "l"(b));
    return r;
}
// zero-cost pair decomposition (register aliasing; no AND/SHF)
__device__ __forceinline__ void unpack2(ull v, float& lo, float& hi) {
    asm("mov.b64 {%0, %1}, %2;" : "=f"(lo), "=f"(hi) : "l"(v));
}
// swizzle pair-index -> physical slot; kills stride-2 LDS.64 bank conflicts
__device__ __forceinline__ int swz(int i) { return i + (i >> 3); }

__global__ __launch_bounds__(128)
void shapelet_kernel(const float* __restrict__ x,
                     const float* __restrict__ w,
                     const float* __restrict__ pcm,
                     float* __restrict__ out)
{
    __shared__ ull    xsm[304];            // swizzled x pairs: pair(t)=(x[2t],x[2t+1])
    __shared__ ull    wneg[NBLK][12];      // 16 shapelets, negated, as pairs
    __shared__ float2 dsm[NBLK][128];      // per-(n, m-pair): (d(m0), d(m0+1))

    const int bc   = blockIdx.x;           // b*C + c
    const int b    = bc >> 3;
    const int c    = bc & 7;
    const int n0   = blockIdx.y * NBLK;
    const int tid  = threadIdx.x;           // 0..127 == m-pair index
    const int lane = tid & 31;
    const int warp = tid >> 5;              // 0..3

    // ---- x row: 256 pairs (swizzled) + zero pad [256..266] ----
    {
        const float2* xrow = (const float2*)(x + bc * TT);
        ((float2*)xsm)[swz(tid)]       = xrow[tid];
        ((float2*)xsm)[swz(tid + 128)] = xrow[tid + 128];
        if (tid < 11) ((float2*)xsm)[swz(256 + tid)] = make_float2(0.f, 0.f);
    }
    // ---- 16 shapelets' weights for channel c, negated (384 floats, strided) ----
    for (int i = tid; i < NBLK * LL; i += 128) {
        const int j = i / LL;
        const int l = i % LL;
        ((float*)wneg)[j * LL + l] = -w[((n0 + j) * CC + c) * LL + l];
    }
    __syncthreads();

    // ---- register window covering m0 = 2*tid and m0+1: xw[k] = pair(m0+k) ----
    const int m0 = 2 * tid;
    ull xw[13];
#pragma unroll
    for (int k = 0; k < 13; ++k) xw[k] = xsm[swz(m0 + k)];

    const float INF = __int_as_float(0x7f800000);
    const float pen0   = (m0     < MM) ? pcm[c * MM + m0]     * (1.0f / (float)LL) : 0.0f;
    const float pen1   = (m0 + 1 < MM) ? pcm[c * MM + m0 + 1] * (1.0f / (float)LL) : 0.0f;
    const float guard0 = (m0     < MM) ? 0.0f : INF;
    const float guard1 = (m0 + 1 < MM) ? 0.0f : INF;

#pragma unroll
    for (int j = 0; j < NBLK; ++j) {
        const ulonglong2* wp = (const ulonglong2*)wneg[j];
        float a0 = 0.f, a1 = 0.f, a2 = 0.f, a3 = 0.f;   // m0
        float b0 = 0.f, b1 = 0.f, b2 = 0.f, b3 = 0.f;   // m0+1
#pragma unroll
        for (int k = 0; k < 6; ++k) {
            const ulonglong2 wv = wp[k];                 // weight pairs 2k, 2k+1
            const ull t0 = add_f32x2(xw[2 * k],     wv.x);  // m0,   wpair 2k
            const ull u0 = add_f32x2(xw[2 * k + 1], wv.x);  // m0+1, wpair 2k
            const ull t1 = add_f32x2(xw[2 * k + 1], wv.y);  // m0,   wpair 2k+1
            const ull u1 = add_f32x2(xw[2 * k + 2], wv.y);  // m0+1, wpair 2k+1
            float lo, hi;
            unpack2(t0, lo, hi);  a0 += fabsf(lo);  a1 += fabsf(hi);
            unpack2(t1, lo, hi);  a2 += fabsf(lo);  a3 += fabsf(hi);
            unpack2(u0, lo, hi);  b0 += fabsf(lo);  b1 += fabsf(hi);
            unpack2(u1, lo, hi);  b2 += fabsf(lo);  b3 += fabsf(hi);
        }
        const float s0 = (a0 + a1) + (a2 + a3);
        const float s1 = (b0 + b1) + (b2 + b3);
        dsm[j][tid] = make_float2(fmaf(s0, pen0, guard0),
                                  fmaf(s1, pen1, guard1));
    }
    __syncthreads();

    // ---- 4 warps reduce 16 rows (warp w -> rows w, w+4, w+8, w+12) ----
#pragma unroll
    for (int rr = 0; rr < 4; ++rr) {
        const int r = warp + rr * 4;
        float mn = INF, mna = INF;
#pragma unroll
        for (int i = 0; i < 4; ++i) {
            const float2 v = dsm[r][lane + i * 32];
            mn  = fminf(mn,  fminf(v.x, v.y));
            mna = fminf(mna, fminf(fabsf(v.x), fabsf(v.y)));   // |src| free on FMNMX
        }
#pragma unroll
        for (int off = 16; off; off >>= 1) {
            mn  = fminf(mn,  __shfl_xor_sync(0xffffffffu, mn,  off));
            mna = fminf(mna, __shfl_xor_sync(0xffffffffu, mna, off));
        }
        if (lane == 0) {
            const int n = n0 + r;
            const int o = (b * NN + n) * CC + c;
            out[o] = expf(-(mna * mna));
            out[BB * NN * CC + o] = mn;
        }
    }
}

extern "C" void kernel_launch(void* const* d_in, const int* in_sizes, int n_in,
                              void* d_out, int out_size)
{
    const float* x   = (const float*)d_in[0];   // (B, C, T)
    const float* w   = (const float*)d_in[1];   // (N, C, L)
    const float* pcm = (const float*)d_in[2];   // (C, M)
    float* out = (float*)d_out;

    dim3 grid(BB * CC, NN / NBLK);              // 128 x 4 = 512 blocks of 128 thr
    shapelet_kernel<<<grid, 128>>>(x, w, pcm, out);
}